// round 2
// baseline (speedup 1.0000x reference)
#include <cuda_runtime.h>

// ---------------------------------------------------------------------------
// Compile-time G(3,0,1) blade algebra (verified round 1, rel_err 8.5e-8).
// Basis order: 0:1 1:e0 2:e1 3:e2 4:e3 5:e01 6:e02 7:e03 8:e12 9:e13 10:e23
//              11:e012 12:e013 13:e023 14:e123 15:e0123
// ---------------------------------------------------------------------------

namespace ga {

__host__ __device__ constexpr int mask_of(int i) {
    const int t[16] = {0, 1, 2, 4, 8, 3, 5, 9, 6, 10, 12, 7, 11, 13, 14, 15};
    return t[i];
}
__host__ __device__ constexpr int idx_of(int m) {
    const int t[16] = {0, 1, 2, 5, 3, 6, 8, 11, 4, 7, 9, 12, 10, 13, 14, 15};
    return t[m];
}
__host__ __device__ constexpr int popc4(int m) {
    return (m & 1) + ((m >> 1) & 1) + ((m >> 2) & 1) + ((m >> 3) & 1);
}
__host__ __device__ constexpr int rsign(int a, int b) {
    int cnt = 0;
    for (int i = 1; i < 4; ++i)
        if ((a >> i) & 1) cnt += popc4(b & ((1 << i) - 1));
    return (cnt & 1) ? -1 : 1;
}

__host__ __device__ constexpr int gp_coef(int k, int j) {
    const int mk = mask_of(k), mj = mask_of(j);
    const int mi = mk ^ mj;
    if (mi & mj & 1) return 0;              // shared e0 -> metric 0
    return rsign(mi, mj);
}
__host__ __device__ constexpr int gp_src(int k, int j) {
    return idx_of(mask_of(k) ^ mask_of(j));
}

__host__ __device__ constexpr int jn_coef(int k, int j) {
    const int mk = mask_of(k), mj = mask_of(j);
    const int nmj = ~mj & 15;
    if (mk & nmj) return 0;                 // requires mk subset of mj
    const int mi = mk | nmj;
    return rsign(~mk & 15, mk)
         * rsign(mi, ~mi & 15)
         * rsign(mj, ~mj & 15)
         * rsign(~mi & 15, nmj);
}
__host__ __device__ constexpr int jn_src(int k, int j) {
    const int mk = mask_of(k), mj = mask_of(j);
    return idx_of(mk | (~mj & 15));
}

// -------- compile-time unrolled accumulators (literal register indices) ----

template <int K, int J>
__device__ __forceinline__ float gp_term(const float (&x)[16], const float (&y)[16]) {
    if constexpr (J >= 16) {
        return 0.0f;
    } else {
        float acc = gp_term<K, J + 1>(x, y);
        constexpr int c = gp_coef(K, J);
        constexpr int p = gp_src(K, J);
        if constexpr (c == 1)  acc = fmaf(x[p], y[J], acc);
        if constexpr (c == -1) acc = fmaf(-x[p], y[J], acc);
        return acc;
    }
}

template <int K, int J>
__device__ __forceinline__ float jn_term(const float (&x)[16], const float (&y)[16]) {
    if constexpr (J >= 16) {
        return 0.0f;
    } else {
        float acc = jn_term<K, J + 1>(x, y);
        constexpr int c = jn_coef(K, J);
        constexpr int p = jn_src(K, J);
        if constexpr (c == 1)  acc = fmaf(x[p], y[J], acc);
        if constexpr (c == -1) acc = fmaf(-x[p], y[J], acc);
        return acc;
    }
}

template <int K>
__device__ __forceinline__ void compute_gp(const float (&x)[16], const float (&y)[16],
                                           float (&o)[16]) {
    if constexpr (K < 16) {
        o[K] = gp_term<K, 0>(x, y);
        compute_gp<K + 1>(x, y, o);
    }
}

template <int K>
__device__ __forceinline__ void compute_jn(const float (&x)[16], const float (&y)[16],
                                           float r15, float (&o)[16]) {
    if constexpr (K < 16) {
        o[K] = r15 * jn_term<K, 0>(x, y);
        compute_jn<K + 1>(x, y, r15, o);
    }
}

}  // namespace ga

// ---------------------------------------------------------------------------
// Kernel: 2 points per thread. All 18 loads front-batched (max MLP), then
// four compute+store phases so only 16 output floats are live at a time.
// Output layout per point: [gp(16), join(16)] = 8 float4.
// ---------------------------------------------------------------------------

__global__ __launch_bounds__(256)
void MVGeometricBilinear_kernel(const float4* __restrict__ x4,
                                const float4* __restrict__ y4,
                                const float* __restrict__ ref,
                                float4* __restrict__ o4,
                                int npts) {
    const int p0 = blockIdx.x * (blockDim.x * 2) + threadIdx.x;
    const int p1 = p0 + blockDim.x;

    if (p1 < npts) {
        // ---- front-batched loads for both points (18 LDG in flight) ----
        float xa[16], ya[16], xb[16], yb[16];
#pragma unroll
        for (int q = 0; q < 4; ++q) {
            const float4 vxa = x4[p0 * 4 + q];
            const float4 vya = y4[p0 * 4 + q];
            const float4 vxb = x4[p1 * 4 + q];
            const float4 vyb = y4[p1 * 4 + q];
            xa[4*q+0]=vxa.x; xa[4*q+1]=vxa.y; xa[4*q+2]=vxa.z; xa[4*q+3]=vxa.w;
            ya[4*q+0]=vya.x; ya[4*q+1]=vya.y; ya[4*q+2]=vya.z; ya[4*q+3]=vya.w;
            xb[4*q+0]=vxb.x; xb[4*q+1]=vxb.y; xb[4*q+2]=vxb.z; xb[4*q+3]=vxb.w;
            yb[4*q+0]=vyb.x; yb[4*q+1]=vyb.y; yb[4*q+2]=vyb.z; yb[4*q+3]=vyb.w;
        }
        const float r15a = __ldg(ref + p0 * 16 + 15);
        const float r15b = __ldg(ref + p1 * 16 + 15);

        float o[16];

        // ---- phase 1: GP(p0) ----
        ga::compute_gp<0>(xa, ya, o);
#pragma unroll
        for (int q = 0; q < 4; ++q)
            o4[p0 * 8 + q] = make_float4(o[4*q+0], o[4*q+1], o[4*q+2], o[4*q+3]);

        // ---- phase 2: GP(p1) ----
        ga::compute_gp<0>(xb, yb, o);
#pragma unroll
        for (int q = 0; q < 4; ++q)
            o4[p1 * 8 + q] = make_float4(o[4*q+0], o[4*q+1], o[4*q+2], o[4*q+3]);

        // ---- phase 3: join(p0) ----
        ga::compute_jn<0>(xa, ya, r15a, o);
#pragma unroll
        for (int q = 0; q < 4; ++q)
            o4[p0 * 8 + 4 + q] = make_float4(o[4*q+0], o[4*q+1], o[4*q+2], o[4*q+3]);

        // ---- phase 4: join(p1) ----
        ga::compute_jn<0>(xb, yb, r15b, o);
#pragma unroll
        for (int q = 0; q < 4; ++q)
            o4[p1 * 8 + 4 + q] = make_float4(o[4*q+0], o[4*q+1], o[4*q+2], o[4*q+3]);
    } else if (p0 < npts) {
        // tail: single point
        float x[16], y[16];
#pragma unroll
        for (int q = 0; q < 4; ++q) {
            const float4 vx = x4[p0 * 4 + q];
            const float4 vy = y4[p0 * 4 + q];
            x[4*q+0]=vx.x; x[4*q+1]=vx.y; x[4*q+2]=vx.z; x[4*q+3]=vx.w;
            y[4*q+0]=vy.x; y[4*q+1]=vy.y; y[4*q+2]=vy.z; y[4*q+3]=vy.w;
        }
        const float r15 = __ldg(ref + p0 * 16 + 15);
        float o[16];
        ga::compute_gp<0>(x, y, o);
#pragma unroll
        for (int q = 0; q < 4; ++q)
            o4[p0 * 8 + q] = make_float4(o[4*q+0], o[4*q+1], o[4*q+2], o[4*q+3]);
        ga::compute_jn<0>(x, y, r15, o);
#pragma unroll
        for (int q = 0; q < 4; ++q)
            o4[p0 * 8 + 4 + q] = make_float4(o[4*q+0], o[4*q+1], o[4*q+2], o[4*q+3]);
    }
}

extern "C" void kernel_launch(void* const* d_in, const int* in_sizes, int n_in,
                              void* d_out, int out_size) {
    const float* x   = (const float*)d_in[0];
    const float* y   = (const float*)d_in[1];
    const float* ref = (const float*)d_in[2];
    float* out       = (float*)d_out;

    const int npts = in_sizes[0] / 16;
    const int threads = 256;
    const int pts_per_block = threads * 2;
    const int blocks = (npts + pts_per_block - 1) / pts_per_block;

    MVGeometricBilinear_kernel<<<blocks, threads>>>(
        (const float4*)x, (const float4*)y, ref, (float4*)out, npts);
}

// round 3
// speedup vs baseline: 1.1084x; 1.1084x over previous
#include <cuda_runtime.h>

// ---------------------------------------------------------------------------
// Compile-time G(3,0,1) blade algebra (verified: rel_err 8.5e-8).
// Basis order: 0:1 1:e0 2:e1 3:e2 4:e3 5:e01 6:e02 7:e03 8:e12 9:e13 10:e23
//              11:e012 12:e013 13:e023 14:e123 15:e0123
// ---------------------------------------------------------------------------

namespace ga {

__host__ __device__ constexpr int mask_of(int i) {
    const int t[16] = {0, 1, 2, 4, 8, 3, 5, 9, 6, 10, 12, 7, 11, 13, 14, 15};
    return t[i];
}
__host__ __device__ constexpr int idx_of(int m) {
    const int t[16] = {0, 1, 2, 5, 3, 6, 8, 11, 4, 7, 9, 12, 10, 13, 14, 15};
    return t[m];
}
__host__ __device__ constexpr int popc4(int m) {
    return (m & 1) + ((m >> 1) & 1) + ((m >> 2) & 1) + ((m >> 3) & 1);
}
__host__ __device__ constexpr int rsign(int a, int b) {
    int cnt = 0;
    for (int i = 1; i < 4; ++i)
        if ((a >> i) & 1) cnt += popc4(b & ((1 << i) - 1));
    return (cnt & 1) ? -1 : 1;
}

__host__ __device__ constexpr int gp_coef(int k, int j) {
    const int mk = mask_of(k), mj = mask_of(j);
    const int mi = mk ^ mj;
    if (mi & mj & 1) return 0;              // shared e0 -> metric 0
    return rsign(mi, mj);
}
__host__ __device__ constexpr int gp_src(int k, int j) {
    return idx_of(mask_of(k) ^ mask_of(j));
}

__host__ __device__ constexpr int jn_coef(int k, int j) {
    const int mk = mask_of(k), mj = mask_of(j);
    const int nmj = ~mj & 15;
    if (mk & nmj) return 0;                 // requires mk subset of mj
    const int mi = mk | nmj;
    return rsign(~mk & 15, mk)
         * rsign(mi, ~mi & 15)
         * rsign(mj, ~mj & 15)
         * rsign(~mi & 15, nmj);
}
__host__ __device__ constexpr int jn_src(int k, int j) {
    const int mk = mask_of(k), mj = mask_of(j);
    return idx_of(mk | (~mj & 15));
}

// -------- compile-time unrolled accumulators (literal register indices) ----

template <int K, int J>
__device__ __forceinline__ float gp_term(const float (&x)[16], const float (&y)[16]) {
    if constexpr (J >= 16) {
        return 0.0f;
    } else {
        float acc = gp_term<K, J + 1>(x, y);
        constexpr int c = gp_coef(K, J);
        constexpr int p = gp_src(K, J);
        if constexpr (c == 1)  acc = fmaf(x[p], y[J], acc);
        if constexpr (c == -1) acc = fmaf(-x[p], y[J], acc);
        return acc;
    }
}

template <int K, int J>
__device__ __forceinline__ float jn_term(const float (&x)[16], const float (&y)[16]) {
    if constexpr (J >= 16) {
        return 0.0f;
    } else {
        float acc = jn_term<K, J + 1>(x, y);
        constexpr int c = jn_coef(K, J);
        constexpr int p = jn_src(K, J);
        if constexpr (c == 1)  acc = fmaf(x[p], y[J], acc);
        if constexpr (c == -1) acc = fmaf(-x[p], y[J], acc);
        return acc;
    }
}

// Compute 4 GP outputs [K..K+3] and return as float4.
template <int K>
__device__ __forceinline__ float4 gp_quad(const float (&x)[16], const float (&y)[16]) {
    return make_float4(gp_term<K + 0, 0>(x, y), gp_term<K + 1, 0>(x, y),
                       gp_term<K + 2, 0>(x, y), gp_term<K + 3, 0>(x, y));
}

// Compute 4 join outputs [K..K+3] (scaled by r15) and return as float4.
template <int K>
__device__ __forceinline__ float4 jn_quad(const float (&x)[16], const float (&y)[16],
                                          float r15) {
    return make_float4(r15 * jn_term<K + 0, 0>(x, y), r15 * jn_term<K + 1, 0>(x, y),
                       r15 * jn_term<K + 2, 0>(x, y), r15 * jn_term<K + 3, 0>(x, y));
}

}  // namespace ga

// ---------------------------------------------------------------------------
// Kernel: 1 point per thread (round-2 showed batching loses to occupancy).
// Streaming loads (__ldcs, no reuse) + streaming stores (__stcs).
// Each output float4 is stored as soon as computed -> peak live set ~45 regs.
// __launch_bounds__(256, 5): 48-reg budget -> 40 warps/SM theoretical.
// ---------------------------------------------------------------------------

__global__ __launch_bounds__(256, 5)
void MVGeometricBilinear_kernel(const float4* __restrict__ x4,
                                const float4* __restrict__ y4,
                                const float* __restrict__ ref,
                                float4* __restrict__ o4,
                                int npts) {
    const int p = blockIdx.x * blockDim.x + threadIdx.x;
    if (p >= npts) return;

    float x[16], y[16];
#pragma unroll
    for (int q = 0; q < 4; ++q) {
        const float4 vx = __ldcs(x4 + p * 4 + q);
        const float4 vy = __ldcs(y4 + p * 4 + q);
        x[4 * q + 0] = vx.x; x[4 * q + 1] = vx.y;
        x[4 * q + 2] = vx.z; x[4 * q + 3] = vx.w;
        y[4 * q + 0] = vy.x; y[4 * q + 1] = vy.y;
        y[4 * q + 2] = vy.z; y[4 * q + 3] = vy.w;
    }
    const float r15 = __ldcs(ref + p * 16 + 15);

    float4* outp = o4 + p * 8;

    // GP outputs, one float4 at a time (store immediately, keep live set small)
    __stcs(outp + 0, ga::gp_quad<0>(x, y));
    __stcs(outp + 1, ga::gp_quad<4>(x, y));
    __stcs(outp + 2, ga::gp_quad<8>(x, y));
    __stcs(outp + 3, ga::gp_quad<12>(x, y));

    // Join outputs
    __stcs(outp + 4, ga::jn_quad<0>(x, y, r15));
    __stcs(outp + 5, ga::jn_quad<4>(x, y, r15));
    __stcs(outp + 6, ga::jn_quad<8>(x, y, r15));
    __stcs(outp + 7, ga::jn_quad<12>(x, y, r15));
}

extern "C" void kernel_launch(void* const* d_in, const int* in_sizes, int n_in,
                              void* d_out, int out_size) {
    const float* x   = (const float*)d_in[0];
    const float* y   = (const float*)d_in[1];
    const float* ref = (const float*)d_in[2];
    float* out       = (float*)d_out;

    const int npts = in_sizes[0] / 16;
    const int threads = 256;
    const int blocks = (npts + threads - 1) / threads;

    MVGeometricBilinear_kernel<<<blocks, threads>>>(
        (const float4*)x, (const float4*)y, ref, (float4*)out, npts);
}